// round 6
// baseline (speedup 1.0000x reference)
#include <cuda_runtime.h>

#define N_PTS 64
#define NA 67   // n + 3
#define NC 69   // augmented columns (NA + 2 RHS)

// Solved TPS weights: w[i*2 + c]; rows 0..63 kernel weights, 64..66 affine.
__device__ float g_w[NA * 2];

// ---------------------------------------------------------------------------
// Kernel 1: fp32 Gauss-Jordan with implicit partial pivoting.
// 1024 threads = 64 rows x 16 lanes (32 warps); rows 64..66 double-assigned
// to threads 0..47. ONE barrier per iteration (double-buffered pcol).
// Pivot search redundant per warp: keys over all 67 rows live in each warp's
// lanes (r0=lane, r1=lane+32, r2=lane+64), REDUX max, then the pivot VALUE is
// pulled by shuffle from the owning lane (no dependent-address LDS).
// ---------------------------------------------------------------------------
__global__ void __launch_bounds__(1024) tps_solve_kernel(
    const float* __restrict__ pts, const float* __restrict__ vals)
{
    __shared__ float M[NA][NC];     // row stride 69 (odd) -> conflict-free
    __shared__ float pcol[2][NA];   // pivot-column values, double-buffered
    __shared__ int   s_prs[NA];     // chosen pivot row per step

    const int tid  = threadIdx.x;
    const int nt   = blockDim.x;
    const int lane = tid & 31;

    // Build augmented matrix [[K, B, Y],[B^T, 0, 0]] in fp32
    for (int idx = tid; idx < NA * NC; idx += nt) {
        int i = idx / NC, j = idx % NC;
        float v = 0.0f;
        if (i < N_PTS) {
            if (j < N_PTS) {
                float dx = pts[2*i]   - pts[2*j];
                float dy = pts[2*i+1] - pts[2*j+1];
                v = sqrtf(fmaf(dx, dx, dy*dy));
            } else if (j < NA) {
                int k = j - N_PTS;
                v = (k == 0) ? 1.0f : pts[2*i + (k-1)];
            } else {
                v = vals[2*i + (j - NA)];
            }
        } else if (j < N_PTS) {
            int k = i - N_PTS;
            v = (k == 0) ? 1.0f : pts[2*j + (k-1)];
        }
        M[i][j] = v;
        if (j == 0) pcol[0][i] = v;
    }
    __syncthreads();

    const int er   = tid >> 4;          // primary row (0..63)
    const int ec   = tid & 15;          // column lane (0..15)
    const bool has2 = (tid < 48);       // threads 0..47 also own rows 64..66
    const int row2 = 64 + er;           // valid only when has2

    // search rows (lane-based; identical across warps)
    const int r0 = lane, r1 = lane + 32, r2 = lane + 64;
    const bool r2ok = (r2 < NA);
    // pivoted-row bitmask (identical in every thread)
    unsigned pm0 = 0, pm1 = 0, pm2 = 0;

    int cur = 0;
    for (int k = 0; k < NA; k++) {
        const int nxt = cur ^ 1;

        // ---- reads of pcol[cur]: search candidates + multiplier numerators
        const float v0 = pcol[cur][r0];
        const float v1 = pcol[cur][r1];
        const float v2 = r2ok ? pcol[cur][r2] : 0.0f;
        const float fnum  = pcol[cur][er];
        const float fnum2 = has2 ? pcol[cur][row2] : 0.0f;

        unsigned key = 0;
        {
            unsigned b = (__float_as_uint(v0) & 0x7FFFFF80u) | (unsigned)r0;
            if (!((pm0 >> lane) & 1u)) key = b;
        }
        {
            unsigned b = (__float_as_uint(v1) & 0x7FFFFF80u) | (unsigned)r1;
            if (!((pm1 >> lane) & 1u) && b > key) key = b;
        }
        if (r2ok) {
            unsigned b = (__float_as_uint(v2) & 0x7FFFFF80u) | (unsigned)r2;
            if (!((pm2 >> lane) & 1u) && b > key) key = b;
        }
        key = __reduce_max_sync(0xFFFFFFFFu, key);
        const int pr = (int)(key & 0x7Fu);
        if (pr < 32)       pm0 |= 1u << pr;
        else if (pr < 64)  pm1 |= 1u << (pr - 32);
        else               pm2 |= 1u << (pr - 64);
        if (tid == 0) s_prs[k] = pr;

        // pivot value via shuffle from the owning lane (no dependent LDS)
        const int slot = pr >> 5;
        float cand = (slot == 0) ? v0 : ((slot == 1) ? v1 : v2);
        const float piv = __shfl_sync(0xFFFFFFFFu, cand, pr & 31);
        const float invpiv = __fdividef(1.0f, piv);

        const float f   = fnum * invpiv;
        const bool  act = (er != pr);

        // ---- elimination: writes M (rows != pr) and pcol[nxt]
        {
            int j = k + 1 + ec;
            if (j < NC) {
                float mv = M[er][j];
                float v  = fmaf(-f, M[pr][j], mv);
                if (act) M[er][j] = v;
                if (ec == 0) pcol[nxt][er] = act ? v : mv;
                #pragma unroll
                for (int u = 0; u < 4; u++) {
                    j += 16;
                    if (j < NC && act) M[er][j] = fmaf(-f, M[pr][j], M[er][j]);
                }
            }
        }
        if (has2) {
            const float f2   = fnum2 * invpiv;
            const bool  act2 = (row2 != pr);
            int j = k + 1 + ec;
            if (j < NC) {
                float mv = M[row2][j];
                float v  = fmaf(-f2, M[pr][j], mv);
                if (act2) M[row2][j] = v;
                if (ec == 0) pcol[nxt][row2] = act2 ? v : mv;
                #pragma unroll
                for (int u = 0; u < 4; u++) {
                    j += 16;
                    if (j < NC && act2) M[row2][j] = fmaf(-f2, M[pr][j], M[row2][j]);
                }
            }
        }
        __syncthreads();
        cur = nxt;
    }

    // extract: w_k = M[pr_k][rhs] / M[pr_k][k]
    if (tid < NA) {
        int pr = s_prs[tid];
        float inv = 1.0f / M[pr][tid];
        g_w[tid*2]   = M[pr][NA]   * inv;
        g_w[tid*2+1] = M[pr][NA+1] * inv;
    }
}

// ---------------------------------------------------------------------------
// Kernel 2: dense evaluation, 4 x-adjacent pixels per thread.
// d^2 = fma(dx,dx, dy^2) (non-negative -> no clamp); sqrt.approx on MUFU;
// 2-channel accumulate via packed fma.rn.f32x2.
// ---------------------------------------------------------------------------
__device__ __forceinline__ float fsqrt_approx(float x) {
    float r;
    asm("sqrt.approx.f32 %0, %1;" : "=f"(r) : "f"(x));
    return r;
}

__device__ __forceinline__ unsigned long long pack2(float lo, float hi) {
    unsigned long long r;
    asm("mov.b64 %0, {%1, %2};" : "=l"(r) : "f"(lo), "f"(hi));
    return r;
}
__device__ __forceinline__ void unpack2(unsigned long long v, float& lo, float& hi) {
    asm("mov.b64 {%0, %1}, %2;" : "=f"(lo), "=f"(hi) : "l"(v));
}

__global__ void __launch_bounds__(128) tps_eval_kernel(
    const float* __restrict__ pts, float* __restrict__ out)
{
    __shared__ float2             sp[N_PTS];   // control point (px, py)
    __shared__ unsigned long long sw[N_PTS];   // packed (w0, w1)
    __shared__ float              aff[6];      // affine weights
    const int tid = threadIdx.x;

    if (tid < N_PTS) {
        sp[tid] = make_float2(pts[2*tid], pts[2*tid+1]);
        sw[tid] = pack2(g_w[2*tid], g_w[2*tid+1]);
    }
    if (tid < 6) aff[tid] = g_w[2*N_PTS + tid];
    __syncthreads();

    const int gid = blockIdx.x * blockDim.x + tid;   // 0 .. 262143
    const int x0  = (gid & 255) << 2;
    const int y   = gid >> 8;

    const float fy = (float)y;
    float fx[4];
    #pragma unroll
    for (int j = 0; j < 4; j++) fx[j] = (float)(x0 + j);

    unsigned long long acc[4];
    #pragma unroll
    for (int j = 0; j < 4; j++) {
        float a0 = fmaf(aff[2], fx[j], fmaf(aff[4], fy, aff[0]));
        float a1 = fmaf(aff[3], fx[j], fmaf(aff[5], fy, aff[1]));
        acc[j] = pack2(a0, a1);
    }

    #pragma unroll 16
    for (int i = 0; i < N_PTS; i++) {
        float2 p = sp[i];
        unsigned long long wv = sw[i];
        float dy  = fy - p.y;
        float dy2 = dy * dy;
        #pragma unroll
        for (int j = 0; j < 4; j++) {
            float dx = fx[j] - p.x;
            float d2 = fmaf(dx, dx, dy2);
            float d  = fsqrt_approx(d2);
            unsigned long long dd = pack2(d, d);
            asm("fma.rn.f32x2 %0, %1, %2, %0;" : "+l"(acc[j]) : "l"(dd), "l"(wv));
        }
    }

    float4 o0, o1;
    unpack2(acc[0], o0.x, o0.y);
    unpack2(acc[1], o0.z, o0.w);
    unpack2(acc[2], o1.x, o1.y);
    unpack2(acc[3], o1.z, o1.w);
    float4* outv = reinterpret_cast<float4*>(out);
    outv[gid*2]   = o0;
    outv[gid*2+1] = o1;
}

// ---------------------------------------------------------------------------
extern "C" void kernel_launch(void* const* d_in, const int* in_sizes, int n_in,
                              void* d_out, int out_size)
{
    const float* pts  = (const float*)d_in[0];
    const float* vals = (const float*)d_in[1];
    float* out = (float*)d_out;

    tps_solve_kernel<<<1, 1024>>>(pts, vals);
    tps_eval_kernel<<<2048, 128>>>(pts, out);
}

// round 7
// speedup vs baseline: 1.3676x; 1.3676x over previous
#include <cuda_runtime.h>

#define N_PTS 64
#define NA 67   // n + 3
#define NC 69   // augmented columns (NA + 2 RHS)

// Solved TPS weights: w[i*2 + c]; rows 0..63 kernel weights, 64..66 affine.
__device__ float g_w[NA * 2];

// ---------------------------------------------------------------------------
// Kernel 1: fp32 Gauss-Jordan with implicit partial pivoting.
// 544 threads = 68 rows x 8 lanes (17 warps; best measured config).
// ONE barrier per iteration: pcol double-buffered (read cur / write nxt).
// Pivot search redundant per warp (REDUX over magnitude keys); pivot VALUE
// comes from a register shuffle off the search candidates (no dependent LDS).
// ---------------------------------------------------------------------------
__global__ void __launch_bounds__(544) tps_solve_kernel(
    const float* __restrict__ pts, const float* __restrict__ vals)
{
    __shared__ float M[NA][NC];     // row stride 69 (odd) -> conflict-free
    __shared__ float pcol[2][NA];   // pivot-column values, double-buffered
    __shared__ int   s_prs[NA];     // chosen pivot row per step

    const int tid  = threadIdx.x;
    const int nt   = blockDim.x;
    const int lane = tid & 31;

    // Build augmented matrix [[K, B, Y],[B^T, 0, 0]] in fp32
    for (int idx = tid; idx < NA * NC; idx += nt) {
        int i = idx / NC, j = idx % NC;
        float v = 0.0f;
        if (i < N_PTS) {
            if (j < N_PTS) {
                float dx = pts[2*i]   - pts[2*j];
                float dy = pts[2*i+1] - pts[2*j+1];
                v = sqrtf(fmaf(dx, dx, dy*dy));
            } else if (j < NA) {
                int k = j - N_PTS;
                v = (k == 0) ? 1.0f : pts[2*i + (k-1)];
            } else {
                v = vals[2*i + (j - NA)];
            }
        } else if (j < N_PTS) {
            int k = i - N_PTS;
            v = (k == 0) ? 1.0f : pts[2*j + (k-1)];
        }
        M[i][j] = v;
        if (j == 0) pcol[0][i] = v;
    }
    __syncthreads();

    const int er = tid >> 3;            // row (0..67; 67 idle)
    const int ec = tid & 7;             // column lane (0..7)
    const bool row_ok = (er < NA);

    // search rows (lane-based; identical across warps)
    const int r0 = lane, r1 = lane + 32, r2 = lane + 64;
    const bool r2ok = (r2 < NA);
    // pivoted-row bitmask (identical in every thread)
    unsigned pm0 = 0, pm1 = 0, pm2 = 0;

    int cur = 0;
    for (int k = 0; k < NA; k++) {
        const int nxt = cur ^ 1;

        // ---- phase A: reads of pcol[cur] only ----
        const float v0 = pcol[cur][r0];
        const float v1 = pcol[cur][r1];
        const float v2 = r2ok ? pcol[cur][r2] : 0.0f;
        const float fnum = pcol[cur][row_ok ? er : 0];   // multiplier numerator

        unsigned key = 0;
        {
            unsigned b = (__float_as_uint(v0) & 0x7FFFFF80u) | (unsigned)r0;
            if (!((pm0 >> lane) & 1u)) key = b;
        }
        {
            unsigned b = (__float_as_uint(v1) & 0x7FFFFF80u) | (unsigned)r1;
            if (!((pm1 >> lane) & 1u) && b > key) key = b;
        }
        if (r2ok) {
            unsigned b = (__float_as_uint(v2) & 0x7FFFFF80u) | (unsigned)r2;
            if (!((pm2 >> lane) & 1u) && b > key) key = b;
        }
        key = __reduce_max_sync(0xFFFFFFFFu, key);
        const int pr = (int)(key & 0x7Fu);
        if (pr < 32)       pm0 |= 1u << pr;
        else if (pr < 64)  pm1 |= 1u << (pr - 32);
        else               pm2 |= 1u << (pr - 64);
        if (tid == 0) s_prs[k] = pr;

        // pivot value: register shuffle from the owning lane
        const int slot = pr >> 5;
        float cand = (slot == 0) ? v0 : ((slot == 1) ? v1 : v2);
        const float piv = __shfl_sync(0xFFFFFFFFu, cand, pr & 31);
        const float invpiv = __fdividef(1.0f, piv);

        const float f   = fnum * invpiv;
        const bool  act = row_ok && (er != pr);

        // ---- phase B: writes to M (rows != pr) and pcol[nxt] ----
        if (row_ok) {
            int j = k + 1 + ec;
            if (j < NC) {
                float mv = M[er][j];
                float v  = fmaf(-f, M[pr][j], mv);
                if (act) M[er][j] = v;
                if (ec == 0) pcol[nxt][er] = act ? v : mv;   // next pivot col
                for (j += 8; j < NC; j += 8) {
                    if (act) M[er][j] = fmaf(-f, M[pr][j], M[er][j]);
                }
            }
        }
        __syncthreads();
        cur = nxt;
    }

    // extract: w_k = M[pr_k][rhs] / M[pr_k][k]
    if (tid < NA) {
        int pr = s_prs[tid];
        float inv = 1.0f / M[pr][tid];
        g_w[tid*2]   = M[pr][NA]   * inv;
        g_w[tid*2+1] = M[pr][NA+1] * inv;
    }
}

// ---------------------------------------------------------------------------
// Kernel 2: dense evaluation, 4 x-adjacent pixels per thread.
// d^2 = fma(dx,dx, dy^2) (non-negative -> no clamp); sqrt.approx on MUFU;
// 2-channel accumulate via packed fma.rn.f32x2.
// ---------------------------------------------------------------------------
__device__ __forceinline__ float fsqrt_approx(float x) {
    float r;
    asm("sqrt.approx.f32 %0, %1;" : "=f"(r) : "f"(x));
    return r;
}

__device__ __forceinline__ unsigned long long pack2(float lo, float hi) {
    unsigned long long r;
    asm("mov.b64 %0, {%1, %2};" : "=l"(r) : "f"(lo), "f"(hi));
    return r;
}
__device__ __forceinline__ void unpack2(unsigned long long v, float& lo, float& hi) {
    asm("mov.b64 {%0, %1}, %2;" : "=f"(lo), "=f"(hi) : "l"(v));
}

__global__ void __launch_bounds__(256) tps_eval_kernel(
    const float* __restrict__ pts, float* __restrict__ out)
{
    __shared__ float2             sp[N_PTS];   // control point (px, py)
    __shared__ unsigned long long sw[N_PTS];   // packed (w0, w1)
    __shared__ float              aff[6];      // affine weights
    const int tid = threadIdx.x;

    if (tid < N_PTS) {
        sp[tid] = make_float2(pts[2*tid], pts[2*tid+1]);
        sw[tid] = pack2(g_w[2*tid], g_w[2*tid+1]);
    }
    if (tid < 6) aff[tid] = g_w[2*N_PTS + tid];
    __syncthreads();

    const int gid = blockIdx.x * blockDim.x + tid;   // 0 .. 262143
    const int x0  = (gid & 255) << 2;
    const int y   = gid >> 8;

    const float fy = (float)y;
    float fx[4];
    #pragma unroll
    for (int j = 0; j < 4; j++) fx[j] = (float)(x0 + j);

    unsigned long long acc[4];
    #pragma unroll
    for (int j = 0; j < 4; j++) {
        float a0 = fmaf(aff[2], fx[j], fmaf(aff[4], fy, aff[0]));
        float a1 = fmaf(aff[3], fx[j], fmaf(aff[5], fy, aff[1]));
        acc[j] = pack2(a0, a1);
    }

    #pragma unroll 16
    for (int i = 0; i < N_PTS; i++) {
        float2 p = sp[i];
        unsigned long long wv = sw[i];
        float dy  = fy - p.y;
        float dy2 = dy * dy;
        #pragma unroll
        for (int j = 0; j < 4; j++) {
            float dx = fx[j] - p.x;
            float d2 = fmaf(dx, dx, dy2);
            float d  = fsqrt_approx(d2);
            unsigned long long dd = pack2(d, d);
            asm("fma.rn.f32x2 %0, %1, %2, %0;" : "+l"(acc[j]) : "l"(dd), "l"(wv));
        }
    }

    float4 o0, o1;
    unpack2(acc[0], o0.x, o0.y);
    unpack2(acc[1], o0.z, o0.w);
    unpack2(acc[2], o1.x, o1.y);
    unpack2(acc[3], o1.z, o1.w);
    float4* outv = reinterpret_cast<float4*>(out);
    outv[gid*2]   = o0;
    outv[gid*2+1] = o1;
}

// ---------------------------------------------------------------------------
extern "C" void kernel_launch(void* const* d_in, const int* in_sizes, int n_in,
                              void* d_out, int out_size)
{
    const float* pts  = (const float*)d_in[0];
    const float* vals = (const float*)d_in[1];
    float* out = (float*)d_out;

    tps_solve_kernel<<<1, 544>>>(pts, vals);
    tps_eval_kernel<<<1024, 256>>>(pts, out);
}